// round 14
// baseline (speedup 1.0000x reference)
#include <cuda_runtime.h>
#include <cstdint>
#include <math.h>

// Problem dims
#define NTOK 4096
#define DDIM 1024
#define NEXP 16
#define HDIM 1536
#define RTOT (2*NTOK)

// GEMM tiling: 128x128 CTA tile, 8 warps of 64x32, BK=16, 4-stage ring
#define BM 128
#define BN 128
#define BK 16
#define STAGES 4
#define STAGE_U32 (BM * BK)              // 2048 u32 per tile per stage
#define STAGE_BYTES (STAGE_U32 * 4 * 2)  // A + B = 16384
#define SM_APTR_BYTES 1024
#define SMEM_DYN (SM_APTR_BYTES + STAGES * STAGE_BYTES)   // 66560

// ---------------- device scratch ----------------
__device__ float g_xs[(size_t)NTOK * DDIM];   // x pre-rounded to tf32
__device__ float g_h[(size_t)RTOT * HDIM];    // hidden, tf32-rounded
__device__ float g_y[(size_t)RTOT * DDIM];
__device__ int   g_perm[RTOT];
__device__ int   g_slot[RTOT];
__device__ float g_gate[RTOT];
__device__ int   g_eid[RTOT];
__device__ int   g_cnt[NEXP];
__device__ int   g_off[NEXP];
__device__ int   g_cur[NEXP];

// ---------------- helpers ----------------
__device__ __forceinline__ uint32_t f2tf(float f) {
    uint32_t r; asm("cvt.rna.tf32.f32 %0, %1;" : "=r"(r) : "f"(f)); return r;
}
__device__ __forceinline__ void mma_tf32(float* c, const uint32_t* a, const uint32_t* b) {
    asm volatile("mma.sync.aligned.m16n8k8.row.col.f32.tf32.tf32.f32 "
        "{%0,%1,%2,%3}, {%4,%5,%6,%7}, {%8,%9}, {%0,%1,%2,%3};"
        : "+f"(c[0]), "+f"(c[1]), "+f"(c[2]), "+f"(c[3])
        : "r"(a[0]), "r"(a[1]), "r"(a[2]), "r"(a[3]), "r"(b[0]), "r"(b[1]));
}
__device__ __forceinline__ void ldsm4(uint32_t addr, uint32_t* r) {
    asm volatile("ldmatrix.sync.aligned.m8n8.x4.shared.b16 {%0,%1,%2,%3}, [%4];"
        : "=r"(r[0]), "=r"(r[1]), "=r"(r[2]), "=r"(r[3]) : "r"(addr));
}
__device__ __forceinline__ void cp16(uint32_t dst, const void* src) {
    asm volatile("cp.async.cg.shared.global [%0], [%1], 16;" :: "r"(dst), "l"(src));
}
__device__ __forceinline__ float gelu_tanh(float v) {
    float u = 0.7978845608028654f * (v + 0.044715f * v * v * v);
    return 0.5f * v * (1.0f + tanhf(u));
}

// ---------------- x -> tf32 pre-round (standalone: streaming-friendly) ------
__global__ void convx_kernel(const float* __restrict__ x) {
    int i = blockIdx.x * blockDim.x + threadIdx.x;
    const int n4 = NTOK * DDIM / 4;
    for (; i < n4; i += gridDim.x * blockDim.x) {
        float4 v = ((const float4*)x)[i];
        uint4 o = { f2tf(v.x), f2tf(v.y), f2tf(v.z), f2tf(v.w) };
        ((uint4*)g_xs)[i] = o;
    }
}

// ---------------- router: one warp per token ----------------
__global__ void router_kernel(const float* __restrict__ x,
                              const float* __restrict__ rw) {
    int warp = (blockIdx.x * blockDim.x + threadIdx.x) >> 5;
    int lane = threadIdx.x & 31;
    if (warp >= NTOK) return;
    const float4* xr = (const float4*)(x + (size_t)warp * DDIM);
    float best1 = -INFINITY, best2 = -INFINITY;
    int i1 = 0, i2 = 0;
    for (int e = 0; e < NEXP; e++) {
        const float4* wr = (const float4*)(rw + (size_t)e * DDIM);
        float s = 0.f;
        #pragma unroll 4
        for (int d = lane; d < DDIM / 4; d += 32) {
            float4 a = xr[d], b = wr[d];
            s += a.x * b.x + a.y * b.y + a.z * b.z + a.w * b.w;
        }
        #pragma unroll
        for (int o = 16; o > 0; o >>= 1) s += __shfl_xor_sync(0xffffffffu, s, o);
        if (s > best1)      { best2 = best1; i2 = i1; best1 = s; i1 = e; }
        else if (s > best2) { best2 = s; i2 = e; }
    }
    if (lane == 0) {
        float t = expf(best2 - best1);
        float denom = 1.0f + t;
        g_eid[2 * warp]     = i1;  g_gate[2 * warp]     = 1.0f / denom;
        g_eid[2 * warp + 1] = i2;  g_gate[2 * warp + 1] = t / denom;
    }
}

// ---------------- count + scan + aux loss (vectorized, deterministic) ------
__global__ void scan_kernel(float* __restrict__ out_tail, int tail_count) {
    __shared__ int   cnt_s[NEXP];
    __shared__ float gs_s[NEXP];
    int w = threadIdx.x >> 5, lane = threadIdx.x & 31;
    if (w < NEXP) {
        int c = 0; float gs = 0.f;
        const int4*   ev = (const int4*)g_eid;
        const float4* gv = (const float4*)g_gate;
        for (int i = lane; i < RTOT / 4; i += 32) {
            int4 e4 = ev[i]; float4 g4 = gv[i];
            if (e4.x == w) { c++; gs += g4.x; }
            if (e4.y == w) { c++; gs += g4.y; }
            if (e4.z == w) { c++; gs += g4.z; }
            if (e4.w == w) { c++; gs += g4.w; }
        }
        #pragma unroll
        for (int o = 16; o > 0; o >>= 1) {
            c  += __shfl_xor_sync(0xffffffffu, c, o);
            gs += __shfl_xor_sync(0xffffffffu, gs, o);
        }
        if (lane == 0) { cnt_s[w] = c; gs_s[w] = gs; }
    }
    __syncthreads();
    if (threadIdx.x == 0) {
        int run = 0; float aux = 0.f;
        for (int e = 0; e < NEXP; e++) {
            g_cnt[e] = cnt_s[e]; g_off[e] = run; g_cur[e] = run; run += cnt_s[e];
            float f = (float)cnt_s[e] / (float)RTOT;
            float m = gs_s[e] / fmaxf((float)cnt_s[e], 1.0f);
            aux += f * m;
        }
        aux = 0.02f * aux / (float)NEXP;
        for (int i = 0; i < tail_count; i++) out_tail[i] = aux;
    }
}

// ---------------- scatter ----------------
__global__ void scatter_kernel() {
    int i = blockIdx.x * blockDim.x + threadIdx.x;
    if (i >= RTOT) return;
    int e = g_eid[i];
    int pos = atomicAdd(&g_cur[e], 1);
    g_perm[pos] = i >> 1;
    g_slot[i] = pos;
}

// ---------------- grouped TF32 GEMM -----------------------------------------
// A: pre-rounded tf32 (g_xs / g_h), 4-stage cp.async ring.
// B: weights f32, LDG -> cvt -> STS in producer (register-staged, distance 2);
//    consumer ldsm reads tf32 bits directly, NO cvt on the mma path.
// Smem stage tile 128r x 16 f32, swizzle c4' = c4 ^ ((r>>1)&3).
template<int KDIM, bool GATHER, bool DOGELU>
__global__ __launch_bounds__(256, 2)
void moe_gemm_kernel(const float* __restrict__ Wbase,   // [E, NTOT, KDIM]
                     const float* __restrict__ Bias,    // [E, NTOT]
                     int NTOT) {
    extern __shared__ __align__(16) char dsm[];
    const float** aptr = (const float**)dsm;
    uint32_t sb = (uint32_t)__cvta_generic_to_shared(dsm) + SM_APTR_BYTES;

    const int e = blockIdx.y;
    const int cnt = g_cnt[e];
    const int m0 = blockIdx.x * BM;
    if (m0 >= cnt) return;
    const int off = g_off[e];
    const int n0 = blockIdx.z * BN;
    const int tid = threadIdx.x;

    const float* Aglob = GATHER ? g_xs : g_h;     // device-side symbol access
    float* Cbase = DOGELU ? g_h : g_y;
    const float* Wp = Wbase + ((size_t)e * NTOT + n0) * KDIM;

    for (int r = tid; r < BM; r += 256) {
        int mi = m0 + r;
        if (mi >= cnt) mi = cnt - 1;
        int row = GATHER ? g_perm[off + mi] : (off + mi);
        aptr[r] = Aglob + (size_t)row * KDIM;
    }
    __syncthreads();

    const int warp = tid >> 5, lane = tid & 31;
    const int wm = (warp & 1) * 64, wn = (warp >> 1) * 32;
    const int gid = lane >> 2, tig = lane & 3;

    // producer coords: 2 x 16B per thread per tile (A and B each)
    const int r0 = tid >> 2, c40 = tid & 3;
    const int r1 = r0 + 64;
    const float* a0 = aptr[r0] + c40 * 4;
    const float* a1 = aptr[r1] + c40 * 4;
    const float* b0 = Wp + (size_t)r0 * KDIM + c40 * 4;
    const float* b1 = Wp + (size_t)r1 * KDIM + c40 * 4;
    const uint32_t o0 = (uint32_t)(r0 * 16 + (c40 ^ ((r0 >> 1) & 3)) * 4) * 4;
    const uint32_t o1 = (uint32_t)(r1 * 16 + (c40 ^ ((r1 >> 1) & 3)) * 4) * 4;

    // consumer ldmatrix base addresses (stage 0)
    const int lm = lane >> 3, lri = lane & 7;
    uint32_t ldA[2][4], ldB[2][2];
    #pragma unroll
    for (int kk = 0; kk < 2; kk++) {
        #pragma unroll
        for (int im = 0; im < 4; im++) {
            int row = wm + im * 16 + (lm & 1) * 8 + lri;
            int c4 = kk * 2 + (lm >> 1);
            int c4s = c4 ^ ((row >> 1) & 3);
            ldA[kk][im] = sb + (uint32_t)(row * 16 + c4s * 4) * 4;
        }
        #pragma unroll
        for (int p = 0; p < 2; p++) {
            int n = wn + (2 * p + (lm >> 1)) * 8 + lri;
            int c4 = kk * 2 + (lm & 1);
            int c4s = c4 ^ ((n >> 1) & 3);
            ldB[kk][p] = sb + (uint32_t)(STAGE_U32 * 4) + (uint32_t)(n * 16 + c4s * 4) * 4;
        }
    }

    auto issue_A = [&](int st, int k0) {
        uint32_t base = sb + (uint32_t)st * STAGE_BYTES;
        cp16(base + o0, a0 + k0);
        cp16(base + o1, a1 + k0);
    };
    auto sts_B = [&](int st, const float4& v0, const float4& v1) {
        uint32_t rel = (uint32_t)st * STAGE_BYTES + (uint32_t)(STAGE_U32 * 4) + SM_APTR_BYTES;
        uint4 u;
        u.x = f2tf(v0.x); u.y = f2tf(v0.y); u.z = f2tf(v0.z); u.w = f2tf(v0.w);
        *(uint4*)(dsm + rel + o0) = u;
        u.x = f2tf(v1.x); u.y = f2tf(v1.y); u.z = f2tf(v1.z); u.w = f2tf(v1.w);
        *(uint4*)(dsm + rel + o1) = u;
    };

    float acc[4][4][4];
    #pragma unroll
    for (int a = 0; a < 4; a++)
        #pragma unroll
        for (int b = 0; b < 4; b++)
            #pragma unroll
            for (int c = 0; c < 4; c++) acc[a][b][c] = 0.f;

    const int KT = KDIM / BK;

    // prologue: B(0) -> smem, B(1) -> regs; A stages 0..2 via cp.async
    float4 vb0 = *(const float4*)b0;
    float4 vb1 = *(const float4*)b1;
    sts_B(0, vb0, vb1);
    #pragma unroll
    for (int p = 0; p < STAGES - 1; p++) {
        issue_A(p, p * BK);
        asm volatile("cp.async.commit_group;");
    }
    vb0 = *(const float4*)(b0 + BK);
    vb1 = *(const float4*)(b1 + BK);

    #pragma unroll 1
    for (int s = 0; s < KT; s++) {
        asm volatile("cp.async.wait_group %0;" :: "n"(STAGES - 2));
        __syncthreads();

        // store B(s+1) from regs (slot (s+1)%4: free, last read at iter s-3)
        if (s + 1 < KT) sts_B((s + 1) & (STAGES - 1), vb0, vb1);
        // issue A(s+3)
        if (s + STAGES - 1 < KT)
            issue_A((s + STAGES - 1) & (STAGES - 1), (s + STAGES - 1) * BK);
        asm volatile("cp.async.commit_group;");
        // load B(s+2) into regs (latency hidden under mma below)
        if (s + 2 < KT) {
            vb0 = *(const float4*)(b0 + (s + 2) * BK);
            vb1 = *(const float4*)(b1 + (s + 2) * BK);
        }

        const uint32_t bofs = (uint32_t)(s & (STAGES - 1)) * STAGE_BYTES;
        #pragma unroll
        for (int kk = 0; kk < 2; kk++) {
            uint32_t af[4][4], bf[4][2];
            #pragma unroll
            for (int im = 0; im < 4; im++)
                ldsm4(ldA[kk][im] + bofs, af[im]);
            #pragma unroll
            for (int p = 0; p < 2; p++) {
                uint32_t bt[4];
                ldsm4(ldB[kk][p] + bofs, bt);
                bf[2 * p][0] = bt[0]; bf[2 * p][1] = bt[1];
                bf[2 * p + 1][0] = bt[2]; bf[2 * p + 1][1] = bt[3];
            }
            #pragma unroll
            for (int im = 0; im < 4; im++)
                #pragma unroll
                for (int in = 0; in < 4; in++)
                    mma_tf32(acc[im][in], af[im], bf[in]);
        }
    }

    // epilogue
    const float* bias_e = Bias + (size_t)e * NTOT;
    #pragma unroll
    for (int im = 0; im < 4; im++) {
        int r0e = m0 + wm + im * 16 + gid;
        #pragma unroll
        for (int in = 0; in < 4; in++) {
            int col = n0 + wn + in * 8 + 2 * tig;
            float bv0 = bias_e[col], bv1 = bias_e[col + 1];
            if (r0e < cnt) {
                float v0 = acc[im][in][0] + bv0;
                float v1 = acc[im][in][1] + bv1;
                if (DOGELU) {
                    v0 = __uint_as_float(f2tf(gelu_tanh(v0)));
                    v1 = __uint_as_float(f2tf(gelu_tanh(v1)));
                }
                size_t base = (size_t)(off + r0e) * NTOT + col;
                Cbase[base] = v0; Cbase[base + 1] = v1;
            }
            if (r0e + 8 < cnt) {
                float v2 = acc[im][in][2] + bv0;
                float v3 = acc[im][in][3] + bv1;
                if (DOGELU) {
                    v2 = __uint_as_float(f2tf(gelu_tanh(v2)));
                    v3 = __uint_as_float(f2tf(gelu_tanh(v3)));
                }
                size_t base = (size_t)(off + r0e + 8) * NTOT + col;
                Cbase[base] = v2; Cbase[base + 1] = v3;
            }
        }
    }
}

// ---------------- combine ----------------
__global__ void combine_kernel(float* __restrict__ out) {
    int n = blockIdx.x;
    int c = threadIdx.x << 2;
    float g0 = g_gate[2 * n], g1 = g_gate[2 * n + 1];
    int s0 = g_slot[2 * n], s1 = g_slot[2 * n + 1];
    float4 y0 = *(const float4*)(g_y + (size_t)s0 * DDIM + c);
    float4 y1 = *(const float4*)(g_y + (size_t)s1 * DDIM + c);
    float4 o;
    o.x = g0 * y0.x + g1 * y1.x;
    o.y = g0 * y0.y + g1 * y1.y;
    o.z = g0 * y0.z + g1 * y1.z;
    o.w = g0 * y0.w + g1 * y1.w;
    *(float4*)(out + (size_t)n * DDIM + c) = o;
}

// ---------------- launch ----------------
extern "C" void kernel_launch(void* const* d_in, const int* in_sizes, int n_in,
                              void* d_out, int out_size) {
    const float* x  = (const float*)d_in[0];
    const float* rw = (const float*)d_in[1];
    const float* w1 = (const float*)d_in[2];
    const float* b1 = (const float*)d_in[3];
    const float* w2 = (const float*)d_in[4];
    const float* b2 = (const float*)d_in[5];
    float* out = (float*)d_out;

    cudaFuncSetAttribute(moe_gemm_kernel<DDIM, true, true>,
                         cudaFuncAttributeMaxDynamicSharedMemorySize, SMEM_DYN);
    cudaFuncSetAttribute(moe_gemm_kernel<HDIM, false, false>,
                         cudaFuncAttributeMaxDynamicSharedMemorySize, SMEM_DYN);

    convx_kernel<<<512, 256>>>(x);
    router_kernel<<<(NTOK * 32 + 255) / 256, 256>>>(x, rw);

    int tail = out_size - NTOK * DDIM;
    if (tail < 0) tail = 0;
    scan_kernel<<<1, 512>>>(out + (size_t)NTOK * DDIM, tail);

    scatter_kernel<<<(RTOT + 255) / 256, 256>>>();

    moe_gemm_kernel<DDIM, true, true><<<dim3(32, NEXP, HDIM / BN), 256, SMEM_DYN>>>(w1, b1, HDIM);
    moe_gemm_kernel<HDIM, false, false><<<dim3(32, NEXP, DDIM / BN), 256, SMEM_DYN>>>(w2, b2, DDIM);

    combine_kernel<<<NTOK, 256>>>(out);
}

// round 15
// speedup vs baseline: 1.0676x; 1.0676x over previous
#include <cuda_runtime.h>
#include <cstdint>
#include <math.h>

// Problem dims
#define NTOK 4096
#define DDIM 1024
#define NEXP 16
#define HDIM 1536
#define RTOT (2*NTOK)

// GEMM tiling: 128x128 CTA tile, 8 warps of 64x32, BK=32, 3-stage cp.async ring
#define BM 128
#define BN 128
#define BK 32
#define STAGES 3
#define STAGE_BYTES (BM * BK * 4 * 2)    // A + B = 32768
#define SM_APTR_BYTES 1024
#define SMEM_DYN (SM_APTR_BYTES + STAGES * STAGE_BYTES)   // 99328

// ---------------- device scratch ----------------
__device__ float g_xs[(size_t)NTOK * DDIM];   // x pre-rounded to tf32
__device__ float g_h[(size_t)RTOT * HDIM];    // hidden, tf32-rounded
__device__ float g_y[(size_t)RTOT * DDIM];
__device__ int   g_perm[RTOT];
__device__ int   g_slot[RTOT];
__device__ float g_gate[RTOT];
__device__ int   g_eid[RTOT];
__device__ int   g_cnt[NEXP];
__device__ int   g_off[NEXP];
__device__ int   g_cur[NEXP];

// ---------------- helpers ----------------
__device__ __forceinline__ uint32_t f2tf(float f) {
    uint32_t r; asm("cvt.rna.tf32.f32 %0, %1;" : "=r"(r) : "f"(f)); return r;
}
__device__ __forceinline__ void mma_tf32(float* c, const uint32_t* a, const uint32_t* b) {
    asm volatile("mma.sync.aligned.m16n8k8.row.col.f32.tf32.tf32.f32 "
        "{%0,%1,%2,%3}, {%4,%5,%6,%7}, {%8,%9}, {%0,%1,%2,%3};"
        : "+f"(c[0]), "+f"(c[1]), "+f"(c[2]), "+f"(c[3])
        : "r"(a[0]), "r"(a[1]), "r"(a[2]), "r"(a[3]), "r"(b[0]), "r"(b[1]));
}
__device__ __forceinline__ void ldsm4(uint32_t addr, uint32_t* r) {
    asm volatile("ldmatrix.sync.aligned.m8n8.x4.shared.b16 {%0,%1,%2,%3}, [%4];"
        : "=r"(r[0]), "=r"(r[1]), "=r"(r[2]), "=r"(r[3]) : "r"(addr));
}
__device__ __forceinline__ void cp16(uint32_t dst, const void* src) {
    asm volatile("cp.async.cg.shared.global [%0], [%1], 16;" :: "r"(dst), "l"(src));
}
__device__ __forceinline__ float gelu_tanh(float v) {
    float u = 0.7978845608028654f * (v + 0.044715f * v * v * v);
    return 0.5f * v * (1.0f + tanhf(u));
}

// ---------------- x -> tf32 pre-round (standalone streaming pass) ----------
__global__ void convx_kernel(const float* __restrict__ x) {
    int i = blockIdx.x * blockDim.x + threadIdx.x;
    const int n4 = NTOK * DDIM / 4;
    for (; i < n4; i += gridDim.x * blockDim.x) {
        float4 v = ((const float4*)x)[i];
        uint4 o = { f2tf(v.x), f2tf(v.y), f2tf(v.z), f2tf(v.w) };
        ((uint4*)g_xs)[i] = o;
    }
}

// ---------------- router: one warp per token ----------------
__global__ void router_kernel(const float* __restrict__ x,
                              const float* __restrict__ rw) {
    int warp = (blockIdx.x * blockDim.x + threadIdx.x) >> 5;
    int lane = threadIdx.x & 31;
    if (warp >= NTOK) return;
    const float4* xr = (const float4*)(x + (size_t)warp * DDIM);
    float best1 = -INFINITY, best2 = -INFINITY;
    int i1 = 0, i2 = 0;
    for (int e = 0; e < NEXP; e++) {
        const float4* wr = (const float4*)(rw + (size_t)e * DDIM);
        float s = 0.f;
        #pragma unroll 4
        for (int d = lane; d < DDIM / 4; d += 32) {
            float4 a = xr[d], b = wr[d];
            s += a.x * b.x + a.y * b.y + a.z * b.z + a.w * b.w;
        }
        #pragma unroll
        for (int o = 16; o > 0; o >>= 1) s += __shfl_xor_sync(0xffffffffu, s, o);
        if (s > best1)      { best2 = best1; i2 = i1; best1 = s; i1 = e; }
        else if (s > best2) { best2 = s; i2 = e; }
    }
    if (lane == 0) {
        float t = expf(best2 - best1);
        float denom = 1.0f + t;
        g_eid[2 * warp]     = i1;  g_gate[2 * warp]     = 1.0f / denom;
        g_eid[2 * warp + 1] = i2;  g_gate[2 * warp + 1] = t / denom;
    }
}

// ---------------- count + scan + aux loss (vectorized, deterministic) ------
__global__ void scan_kernel(float* __restrict__ out_tail, int tail_count) {
    __shared__ int   cnt_s[NEXP];
    __shared__ float gs_s[NEXP];
    int w = threadIdx.x >> 5, lane = threadIdx.x & 31;
    if (w < NEXP) {
        int c = 0; float gs = 0.f;
        const int4*   ev = (const int4*)g_eid;
        const float4* gv = (const float4*)g_gate;
        for (int i = lane; i < RTOT / 4; i += 32) {
            int4 e4 = ev[i]; float4 g4 = gv[i];
            if (e4.x == w) { c++; gs += g4.x; }
            if (e4.y == w) { c++; gs += g4.y; }
            if (e4.z == w) { c++; gs += g4.z; }
            if (e4.w == w) { c++; gs += g4.w; }
        }
        #pragma unroll
        for (int o = 16; o > 0; o >>= 1) {
            c  += __shfl_xor_sync(0xffffffffu, c, o);
            gs += __shfl_xor_sync(0xffffffffu, gs, o);
        }
        if (lane == 0) { cnt_s[w] = c; gs_s[w] = gs; }
    }
    __syncthreads();
    if (threadIdx.x == 0) {
        int run = 0; float aux = 0.f;
        for (int e = 0; e < NEXP; e++) {
            g_cnt[e] = cnt_s[e]; g_off[e] = run; g_cur[e] = run; run += cnt_s[e];
            float f = (float)cnt_s[e] / (float)RTOT;
            float m = gs_s[e] / fmaxf((float)cnt_s[e], 1.0f);
            aux += f * m;
        }
        aux = 0.02f * aux / (float)NEXP;
        for (int i = 0; i < tail_count; i++) out_tail[i] = aux;
    }
}

// ---------------- scatter ----------------
__global__ void scatter_kernel() {
    int i = blockIdx.x * blockDim.x + threadIdx.x;
    if (i >= RTOT) return;
    int e = g_eid[i];
    int pos = atomicAdd(&g_cur[e], 1);
    g_perm[pos] = i >> 1;
    g_slot[i] = pos;
}

// ---------------- grouped TF32 GEMM -----------------------------------------
// A: pre-rounded tf32 (g_xs / g_h) + B: raw f32 weights, BOTH via 3-stage
// cp.async ring; B converted to tf32 after ldmatrix (consumer side).
// Smem stage tile 128 rows x 32 f32 = 128B rows; swizzle c4' = c4 ^ (r&7).
template<int KDIM, bool GATHER, bool DOGELU>
__global__ __launch_bounds__(256, 2)
void moe_gemm_kernel(const float* __restrict__ Wbase,   // [E, NTOT, KDIM]
                     const float* __restrict__ Bias,    // [E, NTOT]
                     int NTOT) {
    extern __shared__ __align__(128) char dsm[];
    const float** aptr = (const float**)dsm;
    uint32_t sb = (uint32_t)__cvta_generic_to_shared(dsm) + SM_APTR_BYTES;

    const int e = blockIdx.y;
    const int cnt = g_cnt[e];
    const int m0 = blockIdx.x * BM;
    if (m0 >= cnt) return;
    const int off = g_off[e];
    const int n0 = blockIdx.z * BN;
    const int tid = threadIdx.x;

    const float* Aglob = GATHER ? g_xs : g_h;     // device-side symbol access
    float* Cbase = DOGELU ? g_h : g_y;
    const float* Wp = Wbase + ((size_t)e * NTOT + n0) * KDIM;

    for (int r = tid; r < BM; r += 256) {
        int mi = m0 + r;
        if (mi >= cnt) mi = cnt - 1;
        int row = GATHER ? g_perm[off + mi] : (off + mi);
        aptr[r] = Aglob + (size_t)row * KDIM;
    }
    __syncthreads();

    const int warp = tid >> 5, lane = tid & 31;
    const int wm = (warp & 1) * 64, wn = (warp >> 1) * 32;
    const int gid = lane >> 2, tig = lane & 3;

    // producer coords: 4 x 16B per thread per tile for A and for B
    // idx = tid + i*256 (i<4): r = idx>>3 (0..127), c4 = idx&7
    int prR[4]; uint32_t prO[4];
    #pragma unroll
    for (int i = 0; i < 4; i++) {
        int idx = tid + i * 256;
        int r = idx >> 3, c4 = idx & 7;
        prR[i] = r;
        prO[i] = (uint32_t)(r * 128 + ((c4 ^ (r & 7)) * 16));
    }
    const int prC4 = tid & 7;  // c4 is the same for all i (idx & 7 == tid & 7)

    // consumer ldmatrix base addresses for kk in {0,1}; kk+2 => addr XOR 64
    const int lm = lane >> 3, lri = lane & 7;
    uint32_t ldA[2][4], ldB[2][2];
    #pragma unroll
    for (int kk = 0; kk < 2; kk++) {
        #pragma unroll
        for (int im = 0; im < 4; im++) {
            int row = wm + im * 16 + (lm & 1) * 8 + lri;
            int c4 = kk * 2 + (lm >> 1);
            int c4s = c4 ^ (row & 7);
            ldA[kk][im] = sb + (uint32_t)(row * 128 + c4s * 16);
        }
        #pragma unroll
        for (int p = 0; p < 2; p++) {
            int n = wn + (2 * p + (lm >> 1)) * 8 + lri;
            int c4 = kk * 2 + (lm & 1);
            int c4s = c4 ^ (n & 7);
            ldB[kk][p] = sb + (uint32_t)(BM * BK * 4) + (uint32_t)(n * 128 + c4s * 16);
        }
    }

    auto issue_stage = [&](int st, int k0) {
        uint32_t baseA = sb + (uint32_t)st * STAGE_BYTES;
        uint32_t baseB = baseA + (uint32_t)(BM * BK * 4);
        #pragma unroll
        for (int i = 0; i < 4; i++) {
            const float* ap = aptr[prR[i]];                     // LDS (cheap, off critical path)
            cp16(baseA + prO[i], ap + k0 + prC4 * 4);
            cp16(baseB + prO[i], Wp + (size_t)prR[i] * KDIM + k0 + prC4 * 4);
        }
    };

    float acc[4][4][4];
    #pragma unroll
    for (int a = 0; a < 4; a++)
        #pragma unroll
        for (int b = 0; b < 4; b++)
            #pragma unroll
            for (int c = 0; c < 4; c++) acc[a][b][c] = 0.f;

    const int KT = KDIM / BK;

    // prologue: stages 0..1
    #pragma unroll
    for (int p = 0; p < STAGES - 1; p++) {
        issue_stage(p, p * BK);
        asm volatile("cp.async.commit_group;");
    }

    #pragma unroll 1
    for (int s = 0; s < KT; s++) {
        asm volatile("cp.async.wait_group %0;" :: "n"(STAGES - 2));
        __syncthreads();

        if (s + STAGES - 1 < KT) {
            int st = s + STAGES - 1;
            issue_stage(st - (st >= STAGES ? STAGES : 0) >= 0 ? (st % STAGES) : 0, st * BK);
        }
        asm volatile("cp.async.commit_group;");   // empty at tail keeps count aligned

        const uint32_t bofs = (uint32_t)(s % STAGES) * STAGE_BYTES;
        #pragma unroll
        for (int kk = 0; kk < 4; kk++) {
            const uint32_t x64 = (kk & 2) ? 64u : 0u;
            const int k2 = kk & 1;
            uint32_t af[4][4], bf[4][2];
            #pragma unroll
            for (int im = 0; im < 4; im++)
                ldsm4((ldA[k2][im] + bofs) ^ x64, af[im]);
            #pragma unroll
            for (int p = 0; p < 2; p++) {
                uint32_t bt[4];
                ldsm4((ldB[k2][p] + bofs) ^ x64, bt);
                bf[2 * p][0]     = f2tf(__uint_as_float(bt[0]));
                bf[2 * p][1]     = f2tf(__uint_as_float(bt[1]));
                bf[2 * p + 1][0] = f2tf(__uint_as_float(bt[2]));
                bf[2 * p + 1][1] = f2tf(__uint_as_float(bt[3]));
            }
            #pragma unroll
            for (int im = 0; im < 4; im++)
                #pragma unroll
                for (int in = 0; in < 4; in++)
                    mma_tf32(acc[im][in], af[im], bf[in]);
        }
    }

    // epilogue
    const float* bias_e = Bias + (size_t)e * NTOT;
    #pragma unroll
    for (int im = 0; im < 4; im++) {
        int r0e = m0 + wm + im * 16 + gid;
        #pragma unroll
        for (int in = 0; in < 4; in++) {
            int col = n0 + wn + in * 8 + 2 * tig;
            float bv0 = bias_e[col], bv1 = bias_e[col + 1];
            if (r0e < cnt) {
                float v0 = acc[im][in][0] + bv0;
                float v1 = acc[im][in][1] + bv1;
                if (DOGELU) {
                    v0 = __uint_as_float(f2tf(gelu_tanh(v0)));
                    v1 = __uint_as_float(f2tf(gelu_tanh(v1)));
                }
                size_t base = (size_t)(off + r0e) * NTOT + col;
                Cbase[base] = v0; Cbase[base + 1] = v1;
            }
            if (r0e + 8 < cnt) {
                float v2 = acc[im][in][2] + bv0;
                float v3 = acc[im][in][3] + bv1;
                if (DOGELU) {
                    v2 = __uint_as_float(f2tf(gelu_tanh(v2)));
                    v3 = __uint_as_float(f2tf(gelu_tanh(v3)));
                }
                size_t base = (size_t)(off + r0e + 8) * NTOT + col;
                Cbase[base] = v2; Cbase[base + 1] = v3;
            }
        }
    }
}

// ---------------- combine ----------------
__global__ void combine_kernel(float* __restrict__ out) {
    int n = blockIdx.x;
    int c = threadIdx.x << 2;
    float g0 = g_gate[2 * n], g1 = g_gate[2 * n + 1];
    int s0 = g_slot[2 * n], s1 = g_slot[2 * n + 1];
    float4 y0 = *(const float4*)(g_y + (size_t)s0 * DDIM + c);
    float4 y1 = *(const float4*)(g_y + (size_t)s1 * DDIM + c);
    float4 o;
    o.x = g0 * y0.x + g1 * y1.x;
    o.y = g0 * y0.y + g1 * y1.y;
    o.z = g0 * y0.z + g1 * y1.z;
    o.w = g0 * y0.w + g1 * y1.w;
    *(float4*)(out + (size_t)n * DDIM + c) = o;
}

// ---------------- launch ----------------
extern "C" void kernel_launch(void* const* d_in, const int* in_sizes, int n_in,
                              void* d_out, int out_size) {
    const float* x  = (const float*)d_in[0];
    const float* rw = (const float*)d_in[1];
    const float* w1 = (const float*)d_in[2];
    const float* b1 = (const float*)d_in[3];
    const float* w2 = (const float*)d_in[4];
    const float* b2 = (const float*)d_in[5];
    float* out = (float*)d_out;

    cudaFuncSetAttribute(moe_gemm_kernel<DDIM, true, true>,
                         cudaFuncAttributeMaxDynamicSharedMemorySize, SMEM_DYN);
    cudaFuncSetAttribute(moe_gemm_kernel<HDIM, false, false>,
                         cudaFuncAttributeMaxDynamicSharedMemorySize, SMEM_DYN);

    convx_kernel<<<512, 256>>>(x);
    router_kernel<<<(NTOK * 32 + 255) / 256, 256>>>(x, rw);

    int tail = out_size - NTOK * DDIM;
    if (tail < 0) tail = 0;
    scan_kernel<<<1, 512>>>(out + (size_t)NTOK * DDIM, tail);

    scatter_kernel<<<(RTOT + 255) / 256, 256>>>();

    moe_gemm_kernel<DDIM, true, true><<<dim3(32, NEXP, HDIM / BN), 256, SMEM_DYN>>>(w1, b1, HDIM);
    moe_gemm_kernel<HDIM, false, false><<<dim3(32, NEXP, DDIM / BN), 256, SMEM_DYN>>>(w2, b2, DDIM);

    combine_kernel<<<NTOK, 256>>>(out);
}